// round 8
// baseline (speedup 1.0000x reference)
#include <cuda_runtime.h>
#include <math.h>
#include <cstdint>
#include <mma.h>

using namespace nvcuda;

// Problem constants
#define BB 16
#define QQ 300
#define CC 256
#define NHH 8
#define DHH 32
#define SUMP 16
#define SS 8500
#define BQ (BB*QQ)        // 4800

#define NTOT 384          // GEMM N
#define KTOT 256          // GEMM K
#define NKS 32            // k-steps of 8
#define NNT 24            // n-tiles of 16

#define DS2 392           // sD row stride (floats)

// scratch
__device__ float g_loc[BQ * 256];
__device__ __align__(16) float gBf[NKS * NNT * 128];  // W in b-fragment order

__device__ __constant__ int cWl[4]    = {80, 40, 20, 10};
__device__ __constant__ int cStart[4] = {0, 6400, 8000, 8400};

__device__ __forceinline__ float tf32r(float x) {
    uint32_t u;
    asm("cvt.rna.tf32.f32 %0, %1;" : "=r"(u) : "f"(x));
    return __uint_as_float(u);
}

typedef wmma::fragment<wmma::matrix_a, 16, 16, 8, wmma::precision::tf32, wmma::row_major> FragA;
typedef wmma::fragment<wmma::matrix_b, 16, 16, 8, wmma::precision::tf32, wmma::row_major> FragB;
typedef wmma::fragment<wmma::accumulator, 16, 16, 8, float> FragC;

// ---------------------------------------------------------------------------
// prep_b: repack [offk | attnk] into b-fragment order + tf32 round.
// One warp per (n-tile, k-step): 768 warps. gBf[(ks*24+nt)*32+lane] = float4.
// ---------------------------------------------------------------------------
__global__ __launch_bounds__(256) void prep_b(const float* __restrict__ offk,
                                              const float* __restrict__ attnk) {
    const int wid  = blockIdx.x * 8 + (threadIdx.x >> 5);
    const int lane = threadIdx.x & 31;
    const int nt = wid >> 5, ks = wid & 31;
    FragB b;
    if (nt < 16)
        wmma::load_matrix_sync(b, offk + (size_t)ks * 8 * 256 + nt * 16, 256);
    else
        wmma::load_matrix_sync(b, attnk + (size_t)ks * 8 * 128 + (nt - 16) * 16, 128);
    float4 v = make_float4(tf32r(b.x[0]), tf32r(b.x[1]), tf32r(b.x[2]), tf32r(b.x[3]));
    ((float4*)gBf)[(size_t)(ks * NNT + nt) * 32 + lane] = v;
}

// ---------------------------------------------------------------------------
// K1: tf32 WMMA GEMM, A fragments loaded directly from hs (gmem) with
// in-register tf32 rounding, B from pre-packed gBf. Fused loc/softmax
// epilogue. Block = 128 (4 warps = 4 n-slices); warp = 2 q-tiles x 6 n-tiles.
// Grid = 150 (32 queries per CTA), one full wave.
// ---------------------------------------------------------------------------
#define SMEM_K1_BYTES (32 * DS2 * 4)   // 50176

__global__ __launch_bounds__(128) void dfine_k1(
    const float* __restrict__ hs,      // (BQ,256)
    const float* __restrict__ refp,    // (BQ,4)
    const float* __restrict__ offb,    // (256,)
    const float* __restrict__ attnb,   // (128,)
    const float* __restrict__ nps,     // (16,)
    float* __restrict__ attn_out)      // (BQ,128)
{
    extern __shared__ float sD[];      // [32][392]
    __shared__ float sRef[32 * 4];

    const int tid  = threadIdx.x;
    const int warp = tid >> 5, lane = tid & 31;
    const int ns   = warp;             // n-slice (0..3), 96 cols each
    const int m0   = blockIdx.x * 32;

    if (tid < 32) ((float4*)sRef)[tid] = ((const float4*)refp)[m0 + tid];

    FragC acc[2][6];
#pragma unroll
    for (int i = 0; i < 2; i++)
#pragma unroll
        for (int j = 0; j < 6; j++) wmma::fill_fragment(acc[i][j], 0.f);

    const float4* pb = (const float4*)gBf + (size_t)ns * 6 * 32 + lane;
    const float* pa0 = hs + (size_t)m0 * KTOT;

#pragma unroll 2
    for (int ks = 0; ks < NKS; ks++) {
        FragA a[2];
#pragma unroll
        for (int i = 0; i < 2; i++) {
            wmma::load_matrix_sync(a[i], pa0 + (size_t)i * 16 * KTOT + ks * 8, KTOT);
#pragma unroll
            for (int e = 0; e < 4; e++) a[i].x[e] = tf32r(a[i].x[e]);
        }
#pragma unroll
        for (int j = 0; j < 6; j++) {
            FragB b;
            float4 bv = pb[(size_t)(ks * NNT + j) * 32];
            b.x[0] = bv.x; b.x[1] = bv.y; b.x[2] = bv.z; b.x[3] = bv.w;
#pragma unroll
            for (int i = 0; i < 2; i++)
                wmma::mma_sync(acc[i][j], a[i], b, acc[i][j]);
        }
    }

    // store D [32 rows][384 cols] to smem
#pragma unroll
    for (int i = 0; i < 2; i++)
#pragma unroll
        for (int j = 0; j < 6; j++)
            wmma::store_matrix_sync(sD + (size_t)i * 16 * DS2 + ns * 96 + j * 16,
                                    acc[i][j], DS2, wmma::mem_row_major);
    __syncthreads();

    // ---- offset epilogue: thread handles cols tid and tid+128, 32 rows ----
#pragma unroll
    for (int half = 0; half < 2; half++) {
        const int j = tid + half * 128;
        const int axis = j & 1, p = (j >> 1) & 15;
        const float bias  = __ldg(offb + j);
        const float scale = __ldg(nps + p) * 0.5f;
#pragma unroll 4
        for (int r = 0; r < 32; r++) {
            float o   = sD[r * DS2 + j];
            float ctr = sRef[r * 4 + axis];
            float wh  = sRef[r * 4 + 2 + axis];
            g_loc[(size_t)(m0 + r) * 256 + j] = fmaf((o + bias) * scale, wh, ctr);
        }
    }

    // ---- attn epilogue: warp handles heads 2w, 2w+1; lane = row ----
#pragma unroll
    for (int hh = 0; hh < 2; hh++) {
        const int h = warp * 2 + hh, r = lane;
        float lg[16];
        float mx = -1e30f;
#pragma unroll
        for (int p = 0; p < 16; p++) {
            lg[p] = sD[r * DS2 + 256 + h * 16 + p] + __ldg(attnb + h * 16 + p);
            mx = fmaxf(mx, lg[p]);
        }
        float s = 0.f;
#pragma unroll
        for (int p = 0; p < 16; p++) { lg[p] = __expf(lg[p] - mx); s += lg[p]; }
        const float inv = 1.f / s;
        float4* dst = (float4*)(attn_out + (size_t)(m0 + r) * 128 + h * 16);
#pragma unroll
        for (int q4 = 0; q4 < 4; q4++)
            dst[q4] = make_float4(lg[q4*4] * inv, lg[q4*4+1] * inv,
                                  lg[q4*4+2] * inv, lg[q4*4+3] * inv);
    }
}

// ---------------------------------------------------------------------------
// K2: per-query gather + weighted accumulate (L2-traffic floor ~29 us).
// ---------------------------------------------------------------------------
__global__ __launch_bounds__(256) void dfine_k2(
    const float* __restrict__ enc,
    const float* __restrict__ attn,
    float* __restrict__ out)
{
    __shared__ int4   sI[128];
    __shared__ float4 sWt[128];

    const int bq = blockIdx.x;
    const int t  = threadIdx.x;
    const int b  = bq / QQ;

    if (t < 128) {
        const int h   = t >> 4;
        const int p   = t & 15;
        const int lvl = p >> 2;
        const int Wl    = cWl[lvl];
        const int start = cStart[lvl];
        const float Wf  = (float)Wl;

        float lx = g_loc[(size_t)bq * 256 + h * 32 + p * 2];
        float ly = g_loc[(size_t)bq * 256 + h * 32 + p * 2 + 1];
        float aw = attn[(size_t)bq * 128 + t];

        float x = lx * Wf - 0.5f;
        float y = ly * Wf - 0.5f;
        float x0f = floorf(x), y0f = floorf(y);
        float fx = x - x0f, fy = y - y0f;
        int x0 = (int)x0f, y0 = (int)y0f;
        int x1 = x0 + 1,   y1 = y0 + 1;

        bool xv0 = ((unsigned)x0 < (unsigned)Wl);
        bool xv1 = ((unsigned)x1 < (unsigned)Wl);
        bool yv0 = ((unsigned)y0 < (unsigned)Wl);
        bool yv1 = ((unsigned)y1 < (unsigned)Wl);

        float w00 = (1.f - fx) * (1.f - fy) * aw;
        float w10 = fx * (1.f - fy) * aw;
        float w01 = (1.f - fx) * fy * aw;
        float w11 = fx * fy * aw;

        int4 I; float4 Wv;
        I.x = (xv0 & yv0) ? start + y0 * Wl + x0 : start;
        I.y = (xv1 & yv0) ? start + y0 * Wl + x1 : start;
        I.z = (xv0 & yv1) ? start + y1 * Wl + x0 : start;
        I.w = (xv1 & yv1) ? start + y1 * Wl + x1 : start;
        Wv.x = (xv0 & yv0) ? w00 : 0.f;
        Wv.y = (xv1 & yv0) ? w10 : 0.f;
        Wv.z = (xv0 & yv1) ? w01 : 0.f;
        Wv.w = (xv1 & yv1) ? w11 : 0.f;

        sI[t]  = I;
        sWt[t] = Wv;
    }
    __syncthreads();

    const int h    = t >> 5;
    const int lane = t & 31;
    const float* vbase = enc + (size_t)b * SS * CC + h * DHH + lane;

    float acc = 0.f;
#pragma unroll
    for (int p = 0; p < SUMP; p++) {
        int4   I  = sI[h * 16 + p];
        float4 Wv = sWt[h * 16 + p];
        acc = fmaf(Wv.x, __ldg(vbase + (size_t)I.x * CC), acc);
        acc = fmaf(Wv.y, __ldg(vbase + (size_t)I.y * CC), acc);
        acc = fmaf(Wv.z, __ldg(vbase + (size_t)I.z * CC), acc);
        acc = fmaf(Wv.w, __ldg(vbase + (size_t)I.w * CC), acc);
    }

    out[(size_t)bq * CC + h * DHH + lane] = acc;
}

// ---------------------------------------------------------------------------
// Launch
// ---------------------------------------------------------------------------
extern "C" void kernel_launch(void* const* d_in, const int* in_sizes, int n_in,
                              void* d_out, int out_size) {
    const float* hs    = (const float*)d_in[0];
    const float* enc   = (const float*)d_in[1];
    const float* refp  = (const float*)d_in[2];
    const float* offk  = (const float*)d_in[3];
    const float* offb  = (const float*)d_in[4];
    const float* attnk = (const float*)d_in[5];
    const float* attnb = (const float*)d_in[6];
    const float* nps   = (const float*)d_in[7];

    float* out      = (float*)d_out;
    float* attn_out = out + (size_t)BQ * CC;

    cudaFuncSetAttribute(dfine_k1, cudaFuncAttributeMaxDynamicSharedMemorySize,
                         SMEM_K1_BYTES);

    prep_b<<<NNT * NKS / 8, 256>>>(offk, attnk);
    dfine_k1<<<150, 128, SMEM_K1_BYTES>>>(hs, refp, offb, attnb, nps, attn_out);
    dfine_k2<<<BQ, 256>>>(enc, attn_out, out);
}

// round 9
// speedup vs baseline: 1.4455x; 1.4455x over previous
#include <cuda_runtime.h>
#include <math.h>
#include <cstdint>
#include <mma.h>

using namespace nvcuda;

// Problem constants
#define BB 16
#define QQ 300
#define CC 256
#define NHH 8
#define DHH 32
#define SUMP 16
#define SS 8500
#define BQ (BB*QQ)        // 4800

#define NTOT 384          // GEMM N
#define KTOT 256          // GEMM K
#define NQT 300           // q-tiles of 16
#define NKS 32            // k-steps of 8
#define NNT 24            // n-tiles of 16

#define DS2 392           // sD row stride (floats)

// scratch
__device__ float g_loc[BQ * 256];
__device__ __align__(16) float gAf[NQT * NKS * 128];  // H in a-fragment order
__device__ __align__(16) float gBf[NKS * NNT * 128];  // W in b-fragment order

__device__ __constant__ int cWl[4]    = {80, 40, 20, 10};
__device__ __constant__ int cStart[4] = {0, 6400, 8000, 8400};

__device__ __forceinline__ float tf32r(float x) {
    uint32_t u;
    asm("cvt.rna.tf32.f32 %0, %1;" : "=r"(u) : "f"(x));
    return __uint_as_float(u);
}

typedef wmma::fragment<wmma::matrix_a, 16, 16, 8, wmma::precision::tf32, wmma::row_major> FragA;
typedef wmma::fragment<wmma::matrix_b, 16, 16, 8, wmma::precision::tf32, wmma::row_major> FragB;
typedef wmma::fragment<wmma::accumulator, 16, 16, 8, float> FragC;

// ---------------------------------------------------------------------------
// prep: repack H into a-fragment order AND W into b-fragment order (+tf32
// rounding), one merged launch. Warps [0,9600) do A; [9600,10368) do B.
// ---------------------------------------------------------------------------
#define A_WARPS (NQT * NKS)          // 9600
#define B_WARPS (NNT * NKS)          // 768
#define PREP_BLOCKS ((A_WARPS + B_WARPS) / 8)   // 1296

__global__ __launch_bounds__(256) void prep(
    const float* __restrict__ hs, const float* __restrict__ offk,
    const float* __restrict__ attnk)
{
    const int wid  = blockIdx.x * 8 + (threadIdx.x >> 5);
    const int lane = threadIdx.x & 31;
    if (wid < A_WARPS) {
        const int qt = wid >> 5, ks = wid & 31;
        FragA a;
        wmma::load_matrix_sync(a, hs + (size_t)qt * 16 * KTOT + ks * 8, KTOT);
        float4 v = make_float4(tf32r(a.x[0]), tf32r(a.x[1]), tf32r(a.x[2]), tf32r(a.x[3]));
        ((float4*)gAf)[(size_t)wid * 32 + lane] = v;
    } else {
        const int w2 = wid - A_WARPS;
        const int nt = w2 >> 5, ks = w2 & 31;
        FragB b;
        if (nt < 16)
            wmma::load_matrix_sync(b, offk + (size_t)ks * 8 * 256 + nt * 16, 256);
        else
            wmma::load_matrix_sync(b, attnk + (size_t)ks * 8 * 128 + (nt - 16) * 16, 128);
        float4 v = make_float4(tf32r(b.x[0]), tf32r(b.x[1]), tf32r(b.x[2]), tf32r(b.x[3]));
        ((float4*)gBf)[(size_t)(ks * NNT + nt) * 32 + lane] = v;
    }
}

// ---------------------------------------------------------------------------
// K1: tf32 WMMA GEMM from pre-packed fragments (all loads coalesced float4)
// + fused loc/softmax epilogue.
// Block = 256 (8 warps = 8 n-slices of 48 cols); warp = 2 q-tiles x 3 n-tiles.
// CTA = 32 queries; grid = 150 -> 2 CTAs/SM, 4 warps/SMSP.
// ---------------------------------------------------------------------------
#define SMEM_K1_BYTES (32 * DS2 * 4)   // 50176

__global__ __launch_bounds__(256, 2) void dfine_k1(
    const float* __restrict__ refp,    // (BQ,4)
    const float* __restrict__ offb,    // (256,)
    const float* __restrict__ attnb,   // (128,)
    const float* __restrict__ nps,     // (16,)
    float* __restrict__ attn_out)      // (BQ,128)
{
    extern __shared__ float sD[];      // [32][392]
    __shared__ float sRef[32 * 4];

    const int tid  = threadIdx.x;
    const int warp = tid >> 5, lane = tid & 31;
    const int ns   = warp;             // n-slice (0..7), 48 cols each
    const int qt0  = blockIdx.x * 2;
    const int m0   = blockIdx.x * 32;

    if (tid < 32) ((float4*)sRef)[tid] = ((const float4*)refp)[m0 + tid];

    FragC acc[2][3];
#pragma unroll
    for (int i = 0; i < 2; i++)
#pragma unroll
        for (int j = 0; j < 3; j++) wmma::fill_fragment(acc[i][j], 0.f);

    const float4* pa = (const float4*)gAf + (size_t)qt0 * NKS * 32 + lane;
    const float4* pb = (const float4*)gBf + (size_t)ns * 3 * 32 + lane;

#pragma unroll 4
    for (int ks = 0; ks < NKS; ks++) {
        FragA a[2];
#pragma unroll
        for (int i = 0; i < 2; i++) {
            float4 av = pa[(size_t)(i * NKS + ks) * 32];
            a[i].x[0] = av.x; a[i].x[1] = av.y; a[i].x[2] = av.z; a[i].x[3] = av.w;
        }
#pragma unroll
        for (int j = 0; j < 3; j++) {
            FragB b;
            float4 bv = pb[(size_t)(ks * NNT + j) * 32];
            b.x[0] = bv.x; b.x[1] = bv.y; b.x[2] = bv.z; b.x[3] = bv.w;
#pragma unroll
            for (int i = 0; i < 2; i++)
                wmma::mma_sync(acc[i][j], a[i], b, acc[i][j]);
        }
    }

    // store D [32 rows][384 cols] to smem
#pragma unroll
    for (int i = 0; i < 2; i++)
#pragma unroll
        for (int j = 0; j < 3; j++)
            wmma::store_matrix_sync(sD + (size_t)i * 16 * DS2 + ns * 48 + j * 16,
                                    acc[i][j], DS2, wmma::mem_row_major);
    __syncthreads();

    // ---- offset epilogue: thread = offset col (0..255), 32 rows ----
    {
        const int j = tid;
        const int axis = j & 1, p = (j >> 1) & 15;
        const float bias  = __ldg(offb + j);
        const float scale = __ldg(nps + p) * 0.5f;
#pragma unroll 4
        for (int r = 0; r < 32; r++) {
            float o   = sD[r * DS2 + j];
            float ctr = sRef[r * 4 + axis];
            float wh  = sRef[r * 4 + 2 + axis];
            g_loc[(size_t)(m0 + r) * 256 + j] = fmaf((o + bias) * scale, wh, ctr);
        }
    }

    // ---- attn epilogue: warp = head, lane = row ----
    {
        const int h = warp, r = lane;
        float lg[16];
        float mx = -1e30f;
#pragma unroll
        for (int p = 0; p < 16; p++) {
            lg[p] = sD[r * DS2 + 256 + h * 16 + p] + __ldg(attnb + h * 16 + p);
            mx = fmaxf(mx, lg[p]);
        }
        float s = 0.f;
#pragma unroll
        for (int p = 0; p < 16; p++) { lg[p] = __expf(lg[p] - mx); s += lg[p]; }
        const float inv = 1.f / s;
        float4* dst = (float4*)(attn_out + (size_t)(m0 + r) * 128 + h * 16);
#pragma unroll
        for (int q4 = 0; q4 < 4; q4++)
            dst[q4] = make_float4(lg[q4*4] * inv, lg[q4*4+1] * inv,
                                  lg[q4*4+2] * inv, lg[q4*4+3] * inv);
    }
}

// ---------------------------------------------------------------------------
// K2: per-query gather + weighted accumulate (L2-traffic floor ~29 us).
// ---------------------------------------------------------------------------
__global__ __launch_bounds__(256) void dfine_k2(
    const float* __restrict__ enc,
    const float* __restrict__ attn,
    float* __restrict__ out)
{
    __shared__ int4   sI[128];
    __shared__ float4 sWt[128];

    const int bq = blockIdx.x;
    const int t  = threadIdx.x;
    const int b  = bq / QQ;

    if (t < 128) {
        const int h   = t >> 4;
        const int p   = t & 15;
        const int lvl = p >> 2;
        const int Wl    = cWl[lvl];
        const int start = cStart[lvl];
        const float Wf  = (float)Wl;

        float lx = g_loc[(size_t)bq * 256 + h * 32 + p * 2];
        float ly = g_loc[(size_t)bq * 256 + h * 32 + p * 2 + 1];
        float aw = attn[(size_t)bq * 128 + t];

        float x = lx * Wf - 0.5f;
        float y = ly * Wf - 0.5f;
        float x0f = floorf(x), y0f = floorf(y);
        float fx = x - x0f, fy = y - y0f;
        int x0 = (int)x0f, y0 = (int)y0f;
        int x1 = x0 + 1,   y1 = y0 + 1;

        bool xv0 = ((unsigned)x0 < (unsigned)Wl);
        bool xv1 = ((unsigned)x1 < (unsigned)Wl);
        bool yv0 = ((unsigned)y0 < (unsigned)Wl);
        bool yv1 = ((unsigned)y1 < (unsigned)Wl);

        float w00 = (1.f - fx) * (1.f - fy) * aw;
        float w10 = fx * (1.f - fy) * aw;
        float w01 = (1.f - fx) * fy * aw;
        float w11 = fx * fy * aw;

        int4 I; float4 Wv;
        I.x = (xv0 & yv0) ? start + y0 * Wl + x0 : start;
        I.y = (xv1 & yv0) ? start + y0 * Wl + x1 : start;
        I.z = (xv0 & yv1) ? start + y1 * Wl + x0 : start;
        I.w = (xv1 & yv1) ? start + y1 * Wl + x1 : start;
        Wv.x = (xv0 & yv0) ? w00 : 0.f;
        Wv.y = (xv1 & yv0) ? w10 : 0.f;
        Wv.z = (xv0 & yv1) ? w01 : 0.f;
        Wv.w = (xv1 & yv1) ? w11 : 0.f;

        sI[t]  = I;
        sWt[t] = Wv;
    }
    __syncthreads();

    const int h    = t >> 5;
    const int lane = t & 31;
    const float* vbase = enc + (size_t)b * SS * CC + h * DHH + lane;

    float acc = 0.f;
#pragma unroll
    for (int p = 0; p < SUMP; p++) {
        int4   I  = sI[h * 16 + p];
        float4 Wv = sWt[h * 16 + p];
        acc = fmaf(Wv.x, __ldg(vbase + (size_t)I.x * CC), acc);
        acc = fmaf(Wv.y, __ldg(vbase + (size_t)I.y * CC), acc);
        acc = fmaf(Wv.z, __ldg(vbase + (size_t)I.z * CC), acc);
        acc = fmaf(Wv.w, __ldg(vbase + (size_t)I.w * CC), acc);
    }

    out[(size_t)bq * CC + h * DHH + lane] = acc;
}

// ---------------------------------------------------------------------------
// Launch
// ---------------------------------------------------------------------------
extern "C" void kernel_launch(void* const* d_in, const int* in_sizes, int n_in,
                              void* d_out, int out_size) {
    const float* hs    = (const float*)d_in[0];
    const float* enc   = (const float*)d_in[1];
    const float* refp  = (const float*)d_in[2];
    const float* offk  = (const float*)d_in[3];
    const float* offb  = (const float*)d_in[4];
    const float* attnk = (const float*)d_in[5];
    const float* attnb = (const float*)d_in[6];
    const float* nps   = (const float*)d_in[7];

    float* out      = (float*)d_out;
    float* attn_out = out + (size_t)BQ * CC;

    cudaFuncSetAttribute(dfine_k1, cudaFuncAttributeMaxDynamicSharedMemorySize,
                         SMEM_K1_BYTES);

    prep<<<PREP_BLOCKS, 256>>>(hs, offk, attnk);
    dfine_k1<<<150, 256, SMEM_K1_BYTES>>>(refp, offb, attnb, nps, attn_out);
    dfine_k2<<<BQ, 256>>>(enc, attn_out, out);
}